// round 8
// baseline (speedup 1.0000x reference)
#include <cuda_runtime.h>
#include <stdint.h>

// StochasticDownsampling2D: out[n,i,j,c] = in[n, rows[i], cols[j], c]
// in:  (8, 512, 512, 64) fp32
// out: (8, 256, 256, 64) fp32
// rows: int32[256], cols: int32[256]
//
// Pure HBM-bound streaming gather. 256 B contiguous per output pixel ->
// copy as float4, 16 float4 per pixel, fully coalesced on both sides.
// No data reuse anywhere -> streaming (.cs) cache hints on the bulk traffic;
// rows/cols stay cached (__ldg) since they're reused by every thread.

#define N_      8
#define H_IN    512
#define W_IN    512
#define C_      64
#define H_OUT   256
#define W_OUT   256
#define C4      (C_ / 4)          // 16 float4 per pixel

// total float4 elements = 8 * 256 * 256 * 16 = 8388608
#define TOTAL4  (N_ * H_OUT * W_OUT * C4)

__global__ __launch_bounds__(256)
void sds2d_kernel(const float4* __restrict__ in4,
                  const int*    __restrict__ rows,
                  const int*    __restrict__ cols,
                  float4*       __restrict__ out4)
{
    unsigned idx = blockIdx.x * 256u + threadIdx.x;   // < TOTAL4 (exact grid)

    // decode: c4 in [0,16), j in [0,256), i in [0,256), n in [0,8)
    unsigned c4 = idx & (C4 - 1);
    unsigned j  = (idx >> 4)  & (W_OUT - 1);
    unsigned i  = (idx >> 12) & (H_OUT - 1);
    unsigned n  = idx >> 20;

    int r  = __ldg(&rows[i]);   // hot, tiny tables: keep cached
    int cj = __ldg(&cols[j]);

    // input float4 offset: ((n*H_IN + r)*W_IN + cj)*C4 + c4
    unsigned src = (((n << 9) + (unsigned)r) << 9 | (unsigned)cj) * C4 + c4;

    // bulk data: read-once / write-once -> streaming hints
    float4 v = __ldcs(&in4[src]);
    __stcs(&out4[idx], v);
}

extern "C" void kernel_launch(void* const* d_in, const int* in_sizes, int n_in,
                              void* d_out, int out_size)
{
    const float4* in4  = (const float4*)d_in[0];
    const int*    rows = (const int*)d_in[1];
    const int*    cols = (const int*)d_in[2];
    float4*       out4 = (float4*)d_out;

    // TOTAL4 = 8388608, 256 threads/block -> 32768 blocks, exact cover
    sds2d_kernel<<<TOTAL4 / 256, 256>>>(in4, rows, cols, out4);
}

// round 11
// speedup vs baseline: 1.0099x; 1.0099x over previous
#include <cuda_runtime.h>
#include <stdint.h>

// StochasticDownsampling2D: out[n,i,j,c] = in[n, rows[i], cols[j], c]
// in:  (8, 512, 512, 64) fp32 -> out: (8, 256, 256, 64) fp32
// rows/cols: int32[256] absolute indices.
//
// R9/R10: unroll x4 (independent float4 per thread, batched loads) to raise
// per-thread MLP 1 -> 4. R8 profile: DRAM=61%, issue=20% -> latency-exposed,
// not bandwidth-saturated. Every LDG/STG stays fully warp-coalesced (512 B
// contiguous per warp per instruction).

#define N_      8
#define H_IN    512
#define W_IN    512
#define C_      64
#define H_OUT   256
#define W_OUT   256
#define C4      (C_ / 4)          // 16 float4 per pixel

#define TOTAL4  (N_ * H_OUT * W_OUT * C4)   // 8388608
#define THREADS 256
#define ITEMS   4
#define PER_BLK (THREADS * ITEMS)           // 1024 float4 per block

__global__ __launch_bounds__(THREADS)
void sds2d_kernel(const float4* __restrict__ in4,
                  const int*    __restrict__ rows,
                  const int*    __restrict__ cols,
                  float4*       __restrict__ out4)
{
    unsigned base = blockIdx.x * (unsigned)PER_BLK + threadIdx.x;

    float4 v[ITEMS];

    // Front-batched independent loads: MLP_p1 = 4
    #pragma unroll
    for (int u = 0; u < ITEMS; u++) {
        unsigned idx = base + u * (unsigned)THREADS;
        unsigned c4  = idx & (C4 - 1);
        unsigned j   = (idx >> 4)  & (W_OUT - 1);
        unsigned i   = (idx >> 12) & (H_OUT - 1);
        unsigned n   = idx >> 20;

        int r  = __ldg(&rows[i]);   // constant across block (L1-hot)
        int cj = __ldg(&cols[j]);

        unsigned src = (((n << 9) + (unsigned)r) << 9 | (unsigned)cj) * C4 + c4;
        v[u] = __ldcs(&in4[src]);
    }

    #pragma unroll
    for (int u = 0; u < ITEMS; u++) {
        __stcs(&out4[base + u * (unsigned)THREADS], v[u]);
    }
}

extern "C" void kernel_launch(void* const* d_in, const int* in_sizes, int n_in,
                              void* d_out, int out_size)
{
    const float4* in4  = (const float4*)d_in[0];
    const int*    rows = (const int*)d_in[1];
    const int*    cols = (const int*)d_in[2];
    float4*       out4 = (float4*)d_out;

    // 8388608 / 1024 = 8192 blocks, exact cover
    sds2d_kernel<<<TOTAL4 / PER_BLK, THREADS>>>(in4, rows, cols, out4);
}